// round 2
// baseline (speedup 1.0000x reference)
#include <cuda_runtime.h>
#include <stdint.h>

// BackEdgeConv2d: out = x * !(5 <= boxcount7x7(x >= 128/255, reflect-pad) <= 19)
// Byte-SWAR separable box filter, one pass, full-width bands.

static constexpr int W      = 1024;
static constexpr int HB     = 32;          // output rows per block
static constexpr int ROWS_P = HB + 6;      // padded rows held in shared (38)
static constexpr int WORDS  = W / 4;       // 256 words of 4 pixels
static constexpr int RSTR   = 260;         // padded row stride in words (need 258)

// bits of float32(128/255) = 0x3F008081 (mantissa 32896.502 rounds UP); K = thresh-1
static constexpr uint32_t KTH = 0x3F008081u - 1u;

// Hardware PRMT (default mode; selector nibble bit3 = sign-replicate). Inline PTX
// because __byte_perm's documented contract covers only digits 0-7.
__device__ __forceinline__ uint32_t prmt(uint32_t a, uint32_t b, uint32_t s)
{
    uint32_t d;
    asm("prmt.b32 %0, %1, %2, %3;" : "=r"(d) : "r"(a), "r"(b), "r"(s));
    return d;
}

__device__ __forceinline__ uint32_t hsum_word(const uint32_t* __restrict__ row, int t)
{
    // padded byte b == pixel b-4. Output word t covers pixels 4t..4t+3.
    // 7-tap window for pixel p needs padded bytes p+1 .. p+7.
    uint32_t A = row[t];        // padded bytes 4t   .. 4t+3
    uint32_t B = row[t + 1];    // padded bytes 4t+4 .. 4t+7
    uint32_t C = row[t + 2];    // padded bytes 4t+8 .. 4t+11
    uint32_t s = B;                              // offset +4
    s += __funnelshift_r(A, B, 8);               // offset +1
    s += __funnelshift_r(A, B, 16);              // offset +2
    s += __funnelshift_r(A, B, 24);              // offset +3
    s += __funnelshift_r(B, C, 8);               // offset +5
    s += __funnelshift_r(B, C, 16);              // offset +6
    s += __funnelshift_r(B, C, 24);              // offset +7
    return s;   // per-byte horizontal count, <= 7
}

__global__ void __launch_bounds__(256)
backedge_kernel(const uint4* __restrict__ x, uint4* __restrict__ out)
{
    __shared__ uint32_t bin_s[ROWS_P * RSTR];   // 38*260*4 = 39520 B (0/1 bytes)
    __shared__ uint32_t hr[8 * WORDS];          // 8192 B ring of hsum rows

    const int t  = threadIdx.x;                 // word column 0..255
    const int y0 = blockIdx.x * HB;             // band start row
    const size_t img_off = (size_t)blockIdx.y * (size_t)W * WORDS;
    const uint4* __restrict__ xi = x + img_off;
    uint4* __restrict__ xo = out + img_off;

    // -------- Phase 1: binarize padded band into shared (packed bytes) --------
    for (int r = 0; r < ROWS_P; ++r) {
        int g = y0 - 3 + r;
        g = (g < 0) ? -g : g;                    // reflect top
        g = (g > W - 1) ? (2 * (W - 1) - g) : g; // reflect bottom
        uint4 v = xi[(size_t)g * WORDS + t];
        // sign(K - u) == 1  iff  u >= thresh  (u >= 0, so int compare == float compare)
        uint32_t s0 = KTH - v.x, s1 = KTH - v.y, s2 = KTH - v.z, s3 = KTH - v.w;
        // PRMT sign-replicate: gather the 4 sign bytes, then mask to 0x01 bytes
        uint32_t p01 = prmt(s0, s1, 0x00FB);     // (sgn s0, sgn s1, -, -)
        uint32_t p23 = prmt(s2, s3, 0x00FB);
        uint32_t w   = prmt(p01, p23, 0x5410) & 0x01010101u;
        bin_s[r * RSTR + t + 1] = w;
        if (t == 0) {
            // left halo word = pixels -4..-1 -> (unused, bin3, bin2, bin1)
            bin_s[r * RSTR] = prmt(w, 0u, 0x1234);
        } else if (t == 255) {
            // right halo word = pixels 1024..1027 -> (bin1022, bin1021, bin1020, unused)
            bin_s[r * RSTR + 257] = prmt(w, 0u, 0x4012);
        }
    }
    __syncthreads();

    // -------- Phase 2: sliding vertical sum of horizontal 7-sums --------
    uint32_t vsum = 0;
    #pragma unroll
    for (int k = 0; k < 6; ++k) {               // warm-up: padded rows 0..5
        uint32_t h = hsum_word(&bin_s[k * RSTR], t);
        vsum += h;
        hr[k * WORDS + t] = h;
    }

    for (int y = 0; y < HB; ++y) {
        uint32_t h = hsum_word(&bin_s[(y + 6) * RSTR], t);
        vsum += h;                               // vsum = rows y-3..y+3, bytes <= 49
        hr[((y + 6) & 7) * WORDS + t] = h;

        // mask byte = 0x80 where 5 <= c <= 19 (no cross-byte carries: c <= 49)
        uint32_t m = (vsum + 0x7B7B7B7Bu) & (0x93939393u - vsum) & 0x80808080u;

        uint4 v = xi[(size_t)(y0 + y) * WORDS + t];   // L2-resident reload
        uint4 o;
        o.x = v.x & ~prmt(m, m, 0x8888);         // replicate sign of byte0 -> 0xFFFFFFFF/0
        o.y = v.y & ~prmt(m, m, 0x9999);
        o.z = v.z & ~prmt(m, m, 0xAAAA);
        o.w = v.w & ~prmt(m, m, 0xBBBB);
        xo[(size_t)(y0 + y) * WORDS + t] = o;

        vsum -= hr[(y & 7) * WORDS + t];         // drop row y-3 (borrow-free)
    }
}

extern "C" void kernel_launch(void* const* d_in, const int* in_sizes, int n_in,
                              void* d_out, int out_size)
{
    const uint4* x = (const uint4*)d_in[0];
    uint4* o = (uint4*)d_out;
    const int nimg = in_sizes[0] / (W * W);      // 16*3 = 48 planes
    dim3 grid(W / HB, nimg);
    backedge_kernel<<<grid, 256>>>(x, o);
}

// round 3
// speedup vs baseline: 1.4801x; 1.4801x over previous
#include <cuda_runtime.h>
#include <stdint.h>

// BackEdgeConv2d: out = x * !(5 <= boxcount7x7(x >= 128/255, reflect-pad) <= 19)
// Vertical-first streaming byte-SWAR box filter: per-row pipeline
//   load(y+3) -> binarize -> vsum(+new,-old via ring) -> shared vsum row ->
//   horizontal 7-tap -> mask -> store.
// Tiny smem footprint (10.3KB) -> 8 blocks/SM; DRAM active every row.

static constexpr int W     = 1024;
static constexpr int HB    = 32;           // output rows per block
static constexpr int WORDS = W / 4;        // 256 words of 4 pixels

// bits of float32(128/255) = 0x3F008081; K = thresh-1 (sign trick, x >= 0)
static constexpr uint32_t KTH = 0x3F008081u - 1u;

__device__ __forceinline__ uint32_t prmt(uint32_t a, uint32_t b, uint32_t s)
{
    uint32_t d;
    asm("prmt.b32 %0, %1, %2, %3;" : "=r"(d) : "r"(a), "r"(b), "r"(s));
    return d;
}

// 4 floats -> packed 0/1 bytes (byte i = pixel 4t+i >= thresh)
__device__ __forceinline__ uint32_t binz(uint4 v)
{
    uint32_t s0 = KTH - v.x, s1 = KTH - v.y, s2 = KTH - v.z, s3 = KTH - v.w;
    uint32_t p01 = prmt(s0, s1, 0x00FB);   // (sgn0, sgn1, 0, 0)
    uint32_t p23 = prmt(s2, s3, 0x00FB);
    return prmt(p01, p23, 0x5410) & 0x01010101u;
}

__device__ __forceinline__ int refl(int g)
{
    g = (g < 0) ? -g : g;
    return (g > W - 1) ? (2 * (W - 1) - g) : g;
}

__global__ void __launch_bounds__(256)
backedge_kernel(const uint4* __restrict__ x, uint4* __restrict__ out)
{
    __shared__ uint32_t ring[8][WORDS];      // per-thread-private binary ring (8KB)
    __shared__ uint32_t vrow[2][WORDS + 4];  // [0]=left halo, 1..256 data, [257]=right halo

    const int t   = threadIdx.x;             // word column 0..255
    const int wid = t >> 5;
    const int y0  = blockIdx.x * HB;
    const size_t off = (size_t)blockIdx.y * (size_t)W * WORDS;
    const uint4* __restrict__ xi = x + off;
    uint4* __restrict__ xo = out + off;

    // ---- warm-up: padded rows 0..5 (image rows y0-3 .. y0+2), 1-deep prefetch ----
    uint32_t vsum = 0;
    uint4 pv = xi[(size_t)refl(y0 - 3) * WORDS + t];
    #pragma unroll
    for (int r = 0; r < 6; ++r) {
        uint4 cur = pv;
        pv = xi[(size_t)refl(y0 - 2 + r) * WORDS + t];    // padded row r+1
        uint32_t b = binz(cur);
        vsum += b;
        ring[r][t] = b;
    }
    // pv = padded row 6 (image y0+3)

    int par = 0;
    for (int y = 0; y < HB; ++y) {
        uint4 cur = pv;                                   // padded row y+6 (image y0+3+y)
        if (y + 1 < HB)
            pv = xi[(size_t)refl(y0 + 4 + y) * WORDS + t]; // prefetch padded row y+7
        uint4 xv = xi[(size_t)(y0 + y) * WORDS + t];       // epilogue x (L1/L2-hot)

        uint32_t b = binz(cur);
        vsum += b;                                        // rows y-3..y+3, bytes <= 7
        ring[(y + 6) & 7][t] = b;

        vrow[par][1 + t] = vsum;
        if (wid == 0) {
            uint32_t w1 = __shfl_down_sync(0xFFFFFFFFu, vsum, 1);
            if (t == 0)                                   // pixels -4..-1 = (v4,v3,v2,v1)
                vrow[par][0] = prmt(vsum, w1, 0x1234);
        } else if (wid == 7) {
            if (t == 255)                                 // pixels 1024.. = (v1022,v1021,v1020,-)
                vrow[par][257] = prmt(vsum, vsum, 0x0012);
        }
        __syncthreads();

        // horizontal 7-tap over vsum bytes: csum byte p = pixels p-3..p+3, <= 49
        uint32_t A = vrow[par][t], B = vrow[par][t + 1], C = vrow[par][t + 2];
        uint32_t c = B
            + __funnelshift_r(A, B, 8)  + __funnelshift_r(A, B, 16) + __funnelshift_r(A, B, 24)
            + __funnelshift_r(B, C, 8)  + __funnelshift_r(B, C, 16) + __funnelshift_r(B, C, 24);

        // mask byte = 0x80 where 5 <= c <= 19
        uint32_t m = (c + 0x7B7B7B7Bu) & (0x93939393u - c) & 0x80808080u;

        uint4 o;
        o.x = xv.x & ~prmt(m, m, 0x8888);  // sign-replicate byte k -> 0xFFFFFFFF / 0
        o.y = xv.y & ~prmt(m, m, 0x9999);
        o.z = xv.z & ~prmt(m, m, 0xAAAA);
        o.w = xv.w & ~prmt(m, m, 0xBBBB);
        xo[(size_t)(y0 + y) * WORDS + t] = o;

        vsum -= ring[y & 7][t];            // drop row y-3 (borrow-free)
        par ^= 1;
    }
}

extern "C" void kernel_launch(void* const* d_in, const int* in_sizes, int n_in,
                              void* d_out, int out_size)
{
    const uint4* x = (const uint4*)d_in[0];
    uint4* o = (uint4*)d_out;
    const int nimg = in_sizes[0] / (W * W);   // 48 planes
    dim3 grid(W / HB, nimg);
    backedge_kernel<<<grid, 256>>>(x, o);
}